// round 9
// baseline (speedup 1.0000x reference)
#include <cuda_runtime.h>
#include <cuda_fp16.h>
#include <math.h>
#include <stdint.h>

#define N_TOK 4096
#define HDIM  1024
#define FDIM  2816
#define NEXP  8
#define NA    (N_TOK * 2)      // assignments (top-2)
#define TM    256              // m-tile rows (one 512-thread CTA)
#define KB    64               // k halves per chunk = 128 B per gmem row-slice
#define ROWB  144              // padded smem row stride (conflict-free ldmatrix, no swizzle)
#define AROWS 256
#define BROWS 128
#define NROWS (AROWS + BROWS)  // 384 rows staged per chunk
#define BOFF  (AROWS * ROWB)   // 36864
#define STAGE (NROWS * ROWB)   // 55296
#define NSTG  3
#define TILE0 64               // tile data starts after mbarriers
#define SMEM_DYN (TILE0 + NSTG * STAGE)
#define MAXMT 40               // max m-tiles: 8192/256 + 8

// ---------------- scratch (static device allocations only) ----------------
__device__ float g_scores[NA];
__device__ int   g_eids[NA];
__device__ int   g_cnt[NEXP];
__device__ int   g_fill[NEXP];
__device__ int   g_off[NEXP + 1];
__device__ int   g_tileoff[NEXP + 1];
__device__ int   g_rows[NA];     // sorted pos -> token
__device__ int   g_aid[NA];      // sorted pos -> assignment id
__device__ __align__(16) __half g_xh[(size_t)N_TOK * HDIM];
__device__ __align__(16) __half g_w1h[(size_t)NEXP * 2 * FDIM * HDIM];
__device__ __align__(16) __half g_w2h[(size_t)NEXP * HDIM * FDIM];
__device__ __align__(16) __half g_Gh[(size_t)NA * FDIM];   // GLU output fp16

// ---------------- helpers ----------------
__device__ __forceinline__ uint32_t smem_u32(const void* p) {
    uint32_t a;
    asm("{ .reg .u64 t; cvta.to.shared.u64 t, %1; cvt.u32.u64 %0, t; }" : "=r"(a) : "l"(p));
    return a;
}
#define MBAR_INIT(mbar, cnt) \
    asm volatile("mbarrier.init.shared.b64 [%0], %1;" :: "r"((uint32_t)(mbar)), "r"((uint32_t)(cnt)) : "memory")
#define ARRIVE_TX(mbar, bytes) \
    asm volatile("mbarrier.arrive.expect_tx.shared::cta.b64 _, [%0], %1;" \
                 :: "r"((uint32_t)(mbar)), "r"((uint32_t)(bytes)) : "memory")
#define BULK128(dst, src, mbar) \
    asm volatile("cp.async.bulk.shared::cta.global.mbarrier::complete_tx::bytes [%0], [%1], 128, [%2];" \
                 :: "r"((uint32_t)(dst)), "l"(src), "r"((uint32_t)(mbar)) : "memory")
#define FENCE_ASYNC_SHARED() asm volatile("fence.proxy.async.shared::cta;" ::: "memory")
#define MBAR_WAIT(mbar, parity) do { \
    uint32_t _m = (uint32_t)(mbar); uint32_t _p = (uint32_t)(parity); uint32_t _d; \
    asm volatile("{\n\t.reg .pred p;\n\t" \
        "mbarrier.try_wait.parity.acquire.cta.shared::cta.b64 p, [%1], %2;\n\t" \
        "selp.b32 %0, 1, 0, p;\n\t}" : "=r"(_d) : "r"(_m), "r"(_p) : "memory"); \
    if (!_d) { \
        asm volatile("{\n\t.reg .pred P1;\n\t" \
            "WL_%=:\n\t" \
            "mbarrier.try_wait.parity.acquire.cta.shared::cta.b64 P1, [%0], %1, 0x989680;\n\t" \
            "@P1 bra.uni WD_%=;\n\t" \
            "bra.uni WL_%=;\n\t" \
            "WD_%=:\n\t}" :: "r"(_m), "r"(_p) : "memory"); \
    } } while (0)
#define LDM4(r0, r1, r2, r3, addr) \
    asm volatile("ldmatrix.sync.aligned.m8n8.x4.shared.b16 {%0,%1,%2,%3},[%4];" \
                 : "=r"(r0), "=r"(r1), "=r"(r2), "=r"(r3) : "r"(addr))
__device__ __forceinline__ void mma16(float* d, const uint32_t* a, uint32_t b0, uint32_t b1) {
    asm volatile(
        "mma.sync.aligned.m16n8k16.row.col.f32.f16.f16.f32 "
        "{%0,%1,%2,%3},{%4,%5,%6,%7},{%8,%9},{%0,%1,%2,%3};"
        : "+f"(d[0]), "+f"(d[1]), "+f"(d[2]), "+f"(d[3])
        : "r"(a[0]), "r"(a[1]), "r"(a[2]), "r"(a[3]), "r"(b0), "r"(b1));
}
// fragment loads (no swizzle: 144B row stride is conflict-free by construction)
#define LDAF(dst, sbase, j) do { \
    LDM4((dst)[0][0], (dst)[0][1], (dst)[0][2], (dst)[0][3], (sbase) + aoff[0] + (j) * 32); \
    LDM4((dst)[1][0], (dst)[1][1], (dst)[1][2], (dst)[1][3], (sbase) + aoff[1] + (j) * 32); \
} while (0)
#define LDBF(dst, sbase, j, p) \
    LDM4((dst)[0], (dst)[1], (dst)[2], (dst)[3], (sbase) + boff[p] + (j) * 32)

// ---------------- launch 0: fp32 -> fp16 weight convert (+ counter init) ------
__global__ void convert_kernel(const float* __restrict__ w1, const float* __restrict__ w2) {
    if (blockIdx.x == 0 && threadIdx.x < NEXP) {
        g_cnt[threadIdx.x] = 0; g_fill[threadIdx.x] = 0;
    }
    const size_t U1 = (size_t)NEXP * 2 * FDIM * HDIM / 8;
    const size_t U2 = (size_t)NEXP * HDIM * FDIM / 8;
    const size_t i = (size_t)blockIdx.x * blockDim.x + threadIdx.x;
    const float* src;
    __half* dst;
    if (i < U1)           { src = w1 + i * 8;        dst = g_w1h + i * 8; }
    else if (i < U1 + U2) { src = w2 + (i - U1) * 8; dst = g_w2h + (i - U1) * 8; }
    else return;
    const float4 v0 = ((const float4*)src)[0];
    const float4 v1 = ((const float4*)src)[1];
    __half2 h0 = __floats2half2_rn(v0.x, v0.y);
    __half2 h1 = __floats2half2_rn(v0.z, v0.w);
    __half2 h2 = __floats2half2_rn(v1.x, v1.y);
    __half2 h3 = __floats2half2_rn(v1.z, v1.w);
    uint4 o;
    o.x = *(uint32_t*)&h0; o.y = *(uint32_t*)&h1;
    o.z = *(uint32_t*)&h2; o.w = *(uint32_t*)&h3;
    *(uint4*)dst = o;
}

// ---------------- launch 1: router (+ x fp16 convert) ----------------
__global__ __launch_bounds__(256) void router_kernel(const float* __restrict__ x,
                                                     const float* __restrict__ wqkv) {
    __shared__ float sx[HDIM];
    __shared__ float sqkv[3 * NEXP];
    const int t = blockIdx.x;
    const float* xr = x + (size_t)t * HDIM;
    for (int i = threadIdx.x; i < HDIM; i += blockDim.x) sx[i] = xr[i];
    __syncthreads();

    for (int i = threadIdx.x; i < HDIM; i += blockDim.x)
        g_xh[(size_t)t * HDIM + i] = __float2half(sx[i]);

    const int w = threadIdx.x >> 5, lane = threadIdx.x & 31;
    #pragma unroll
    for (int r = 0; r < 3; r++) {
        const int j = w + r * NEXP;
        const float* wr = wqkv + (size_t)j * HDIM;
        float s = 0.f;
        for (int i = lane; i < HDIM; i += 32) s += sx[i] * wr[i];
        #pragma unroll
        for (int o = 16; o; o >>= 1) s += __shfl_xor_sync(0xffffffffu, s, o);
        if (lane == 0) sqkv[j] = s;
    }
    __syncthreads();

    if (w == 0) {
        float logit = -1e30f;
        if (lane < NEXP) {
            const float qe = sqkv[lane];
            float a[NEXP], m = -1e30f;
            #pragma unroll
            for (int j = 0; j < NEXP; j++) { a[j] = qe * sqkv[8 + j]; m = fmaxf(m, a[j]); }
            float den = 0.f, num = 0.f;
            #pragma unroll
            for (int j = 0; j < NEXP; j++) {
                float ee = expf(a[j] - m);
                den += ee; num += ee * sqkv[16 + j];
            }
            logit = num / den;
        }
        float lg[NEXP];
        #pragma unroll
        for (int e = 0; e < NEXP; e++) lg[e] = __shfl_sync(0xffffffffu, logit, e);
        if (lane == 0) {
            int i0 = 0;
            #pragma unroll
            for (int e = 1; e < NEXP; e++) if (lg[e] > lg[i0]) i0 = e;
            int i1 = (i0 == 0) ? 1 : 0;
            #pragma unroll
            for (int e = 0; e < NEXP; e++) if (e != i1 && e != i0 && lg[e] > lg[i1]) i1 = e;
            const float e1 = expf(lg[i1] - lg[i0]);
            const float inv = 1.f / (1.f + e1);
            g_scores[2 * t]     = inv;
            g_scores[2 * t + 1] = e1 * inv;
            g_eids[2 * t]     = i0;
            g_eids[2 * t + 1] = i1;
            atomicAdd(&g_cnt[i0], 1);
            atomicAdd(&g_cnt[i1], 1);
        }
    }
}

// ---------------- launch 2: scatter (each block re-derives the 8-expert scan) --
__global__ void scatter_kernel() {
    int off[NEXP + 1], tileoff[NEXP + 1];
    int o = 0, tt = 0;
    #pragma unroll
    for (int e = 0; e < NEXP; e++) {
        off[e] = o; tileoff[e] = tt;
        o += g_cnt[e];
        tt += (g_cnt[e] + TM - 1) / TM;
    }
    off[NEXP] = o; tileoff[NEXP] = tt;

    if (blockIdx.x == 0 && threadIdx.x == 0) {
        #pragma unroll
        for (int e = 0; e <= NEXP; e++) { g_off[e] = off[e]; g_tileoff[e] = tileoff[e]; }
    }

    const int a = blockIdx.x * blockDim.x + threadIdx.x;
    if (a < NA) {
        const int e = g_eids[a];
        const int p = off[e] + atomicAdd(&g_fill[e], 1);
        g_aid[p]  = a;
        g_rows[p] = a >> 1;
    }
}

// ---------------- launch 3: grouped GEMM1 (bulk-async + fp16 HMMA) + GLU ------
// One 512-thread CTA: M=256 sorted rows x 64 GLU cols (B = 128 a/g-interleaved
// w1 rows). Staging: 384 x 128B cp.async.bulk per chunk into 144B-stride rows.
__global__ __launch_bounds__(512, 1) void gemm1_kernel() {
    const int mt = blockIdx.x;
    if (mt >= g_tileoff[NEXP]) return;
    int e = 0;
    #pragma unroll
    for (int i = 1; i < NEXP; i++) if (g_tileoff[i] <= mt) e = i;
    const int pbase = g_off[e];
    const int cnt   = g_off[e + 1] - pbase;
    const int m0    = (mt - g_tileoff[e]) * TM;
    const int nb    = blockIdx.y * 64;            // GLU col base

    extern __shared__ __align__(128) char smem[];
    const uint32_t sb = smem_u32(smem);
    const int tid = threadIdx.x, wid = tid >> 5, lane = tid & 31;
    const int wm = wid & 7, wn = wid >> 3;
    const int sel = lane >> 3, li = lane & 7;
    const int g = lane >> 2, tg = lane & 3;

    if (tid == 0) {
        MBAR_INIT(sb + 0, NROWS); MBAR_INIT(sb + 8, NROWS); MBAR_INIT(sb + 16, NROWS);
        FENCE_ASYNC_SHARED();
    }
    __syncthreads();

    // per-thread bulk-issue source (row tid) and stage-0 destination
    const char* gsrc = nullptr;
    uint32_t dst0 = 0;
    if (tid < AROWS) {
        int am = m0 + tid; if (am >= cnt) am = cnt - 1;
        gsrc = (const char*)(g_xh + (size_t)g_rows[pbase + am] * HDIM);
        dst0 = sb + TILE0 + tid * ROWB;
    } else if (tid < NROWS) {
        const int rb = tid - AROWS;
        const int wrow = e * 2 * FDIM + ((rb & 1) ? FDIM : 0) + nb + (rb >> 1);  // a/g interleave
        gsrc = (const char*)(g_w1h + (size_t)wrow * HDIM);
        dst0 = sb + TILE0 + BOFF + rb * ROWB;
    }

    uint32_t aoff[2], boff[4];
    #pragma unroll
    for (int mi = 0; mi < 2; mi++)
        aoff[mi] = TILE0 + (uint32_t)(wm * 32 + mi * 16 + (sel & 1) * 8 + li) * ROWB + (sel >> 1) * 16;
    #pragma unroll
    for (int p = 0; p < 4; p++)
        boff[p] = TILE0 + BOFF + (uint32_t)(wn * 64 + p * 16 + (sel >> 1) * 8 + li) * ROWB + (sel & 1) * 16;

    float acc[2][8][4];
    #pragma unroll
    for (int mi = 0; mi < 2; mi++)
        #pragma unroll
        for (int ni = 0; ni < 8; ni++)
            #pragma unroll
            for (int q = 0; q < 4; q++) acc[mi][ni][q] = 0.f;

    const int NC = HDIM / KB;  // 16
    // prologue: stage chunks 0 and 1
    if (tid < NROWS) {
        ARRIVE_TX(sb + 0, 128); BULK128(dst0, gsrc, sb + 0);
        ARRIVE_TX(sb + 8, 128); BULK128(dst0 + STAGE, gsrc + 128, sb + 8);
    }

    uint32_t af[2][2][4], bf[2][4];
    for (int c = 0; c < NC; c++) {
        const int s = c % NSTG;
        const uint32_t sbase = sb + s * STAGE;
        MBAR_WAIT(sb + s * 8, (c / NSTG) & 1);
        LDAF(af[0], sbase, 0);
        LDBF(bf[0], sbase, 0, 0);
        #pragma unroll
        for (int j = 0; j < 4; j++) {
            #pragma unroll
            for (int p = 0; p < 4; p++) {
                if (p < 3) {
                    LDBF(bf[(p + 1) & 1], sbase, j, p + 1);
                } else if (j < 3) {
                    LDAF(af[(j + 1) & 1], sbase, j + 1);
                    LDBF(bf[0], sbase, j + 1, 0);
                }
                #pragma unroll
                for (int mi = 0; mi < 2; mi++) {
                    mma16(acc[mi][2 * p],     af[j & 1][mi], bf[p & 1][0], bf[p & 1][1]);
                    mma16(acc[mi][2 * p + 1], af[j & 1][mi], bf[p & 1][2], bf[p & 1][3]);
                }
            }
        }
        __syncthreads();   // all warps done reading stage (c+2)%3's previous contents
        if (c + 2 < NC && tid < NROWS) {
            const int s2 = (c + 2) % NSTG;
            ARRIVE_TX(sb + s2 * 8, 128);
            BULK128(dst0 + s2 * STAGE, gsrc + (size_t)(c + 2) * 128, sb + s2 * 8);
        }
    }

    // GLU epilogue: even/odd acc col = (a, g) of GLU col 4*ni + tg (within warp block)
    #pragma unroll
    for (int mi = 0; mi < 2; mi++)
        #pragma unroll
        for (int h = 0; h < 2; h++) {
            const int m = m0 + wm * 32 + mi * 16 + g + h * 8;
            if (m < cnt) {
                __half* gp = g_Gh + (size_t)(pbase + m) * FDIM + nb + wn * 32;
                #pragma unroll
                for (int ni = 0; ni < 8; ni++) {
                    const float a  = acc[mi][ni][h * 2];
                    const float gg = acc[mi][ni][h * 2 + 1];
                    gp[ni * 4 + tg] = __float2half(a / (1.f + expf(-a)) * gg);
                }
            }
        }
}

// ---------------- launch 4: zero output ----------------
__global__ void zero_kernel(float* __restrict__ out) {
    const int i = blockIdx.x * blockDim.x + threadIdx.x;
    if (i < N_TOK * HDIM / 4) ((float4*)out)[i] = make_float4(0.f, 0.f, 0.f, 0.f);
}

// ---------------- launch 5: grouped GEMM2 (bulk-async + fp16 HMMA) ------------
// M=256 sorted G rows x 128 out cols, K=2816; atomic top-2 combine epilogue.
__global__ __launch_bounds__(512, 1) void gemm2_kernel(float* __restrict__ out) {
    const int mt = blockIdx.x;
    if (mt >= g_tileoff[NEXP]) return;
    int e = 0;
    #pragma unroll
    for (int i = 1; i < NEXP; i++) if (g_tileoff[i] <= mt) e = i;
    const int pbase = g_off[e];
    const int cnt   = g_off[e + 1] - pbase;
    const int m0    = (mt - g_tileoff[e]) * TM;
    const int nb    = blockIdx.y * 128;           // output col base

    extern __shared__ __align__(128) char smem[];
    const uint32_t sb = smem_u32(smem);
    const int tid = threadIdx.x, wid = tid >> 5, lane = tid & 31;
    const int wm = wid & 7, wn = wid >> 3;
    const int sel = lane >> 3, li = lane & 7;
    const int g = lane >> 2, tg = lane & 3;

    if (tid == 0) {
        MBAR_INIT(sb + 0, NROWS); MBAR_INIT(sb + 8, NROWS); MBAR_INIT(sb + 16, NROWS);
        FENCE_ASYNC_SHARED();
    }
    __syncthreads();

    const char* gsrc = nullptr;
    uint32_t dst0 = 0;
    if (tid < AROWS) {
        int am = m0 + tid; if (am >= cnt) am = cnt - 1;
        gsrc = (const char*)(g_Gh + (size_t)(pbase + am) * FDIM);
        dst0 = sb + TILE0 + tid * ROWB;
    } else if (tid < NROWS) {
        const int rb = tid - AROWS;
        gsrc = (const char*)(g_w2h + ((size_t)e * HDIM + nb + rb) * FDIM);
        dst0 = sb + TILE0 + BOFF + rb * ROWB;
    }

    uint32_t aoff[2], boff[4];
    #pragma unroll
    for (int mi = 0; mi < 2; mi++)
        aoff[mi] = TILE0 + (uint32_t)(wm * 32 + mi * 16 + (sel & 1) * 8 + li) * ROWB + (sel >> 1) * 16;
    #pragma unroll
    for (int p = 0; p < 4; p++)
        boff[p] = TILE0 + BOFF + (uint32_t)(wn * 64 + p * 16 + (sel >> 1) * 8 + li) * ROWB + (sel & 1) * 16;

    float acc[2][8][4];
    #pragma unroll
    for (int mi = 0; mi < 2; mi++)
        #pragma unroll
        for (int ni = 0; ni < 8; ni++)
            #pragma unroll
            for (int q = 0; q < 4; q++) acc[mi][ni][q] = 0.f;

    const int NC = FDIM / KB;  // 44
    if (tid < NROWS) {
        ARRIVE_TX(sb + 0, 128); BULK128(dst0, gsrc, sb + 0);
        ARRIVE_TX(sb + 8, 128); BULK128(dst0 + STAGE, gsrc + 128, sb + 8);
    }

    uint32_t af[2][2][4], bf[2][4];
    for (int c = 0; c < NC; c++) {
        const int s = c % NSTG;
        const uint32_t sbase = sb + s * STAGE;
        MBAR_WAIT(sb + s * 8, (c / NSTG) & 1);
        LDAF(af[0], sbase, 0);
        LDBF(bf[0], sbase, 0, 0);
        #pragma unroll
        for (int j = 0; j < 4; j++) {
            #pragma unroll
            for (int p = 0; p < 4; p++) {
                if (p < 3) {
                    LDBF(bf[(p + 1) & 1], sbase, j, p + 1);
                } else if (j < 3) {
                    LDAF(af[(j + 1) & 1], sbase, j + 1);
                    LDBF(bf[0], sbase, j + 1, 0);
                }
                #pragma unroll
                for (int mi = 0; mi < 2; mi++) {
                    mma16(acc[mi][2 * p],     af[j & 1][mi], bf[p & 1][0], bf[p & 1][1]);
                    mma16(acc[mi][2 * p + 1], af[j & 1][mi], bf[p & 1][2], bf[p & 1][3]);
                }
            }
        }
        __syncthreads();
        if (c + 2 < NC && tid < NROWS) {
            const int s2 = (c + 2) % NSTG;
            ARRIVE_TX(sb + s2 * 8, 128);
            BULK128(dst0 + s2 * STAGE, gsrc + (size_t)(c + 2) * 128, sb + s2 * 8);
        }
    }

    // epilogue: scale by routing score, atomic top-2 combine (2 adds/cell -> deterministic)
    #pragma unroll
    for (int mi = 0; mi < 2; mi++)
        #pragma unroll
        for (int h = 0; h < 2; h++) {
            const int m = m0 + wm * 32 + mi * 16 + g + h * 8;
            if (m < cnt) {
                const int aid  = g_aid[pbase + m];
                const float sc = g_scores[aid];
                float* op = out + (size_t)(aid >> 1) * HDIM + nb + wn * 64;
                #pragma unroll
                for (int ni = 0; ni < 8; ni++) {
                    const int c0 = ni * 8 + 2 * tg;
                    atomicAdd(op + c0,     sc * acc[mi][ni][h * 2]);
                    atomicAdd(op + c0 + 1, sc * acc[mi][ni][h * 2 + 1]);
                }
            }
        }
}

// ---------------- launch ----------------
extern "C" void kernel_launch(void* const* d_in, const int* in_sizes, int n_in,
                              void* d_out, int out_size) {
    const float* x    = (const float*)d_in[0];  // (2,2048,1024)
    const float* wqkv = (const float*)d_in[1];  // (24,1024)
    const float* w1   = (const float*)d_in[2];  // (8,5632,1024)
    const float* w2   = (const float*)d_in[3];  // (8,1024,2816)
    float* out = (float*)d_out;

    cudaFuncSetAttribute(gemm1_kernel, cudaFuncAttributeMaxDynamicSharedMemorySize, SMEM_DYN);
    cudaFuncSetAttribute(gemm2_kernel, cudaFuncAttributeMaxDynamicSharedMemorySize, SMEM_DYN);

    const int conv_units = (NEXP * 2 * FDIM * HDIM + NEXP * HDIM * FDIM) / 8;
    convert_kernel<<<(conv_units + 255) / 256, 256>>>(w1, w2);            // 0
    router_kernel<<<N_TOK, 256>>>(x, wqkv);                               // 1
    scatter_kernel<<<(NA + 255) / 256, 256>>>();                          // 2
    gemm1_kernel<<<dim3(MAXMT, FDIM / 64), 512, SMEM_DYN>>>();            // 3  <- profiled
    zero_kernel<<<(N_TOK * HDIM / 4 + 255) / 256, 256>>>(out);            // 4
    gemm2_kernel<<<dim3(MAXMT, HDIM / 128), 512, SMEM_DYN>>>(out);        // 5
}

// round 10
// speedup vs baseline: 1.1850x; 1.1850x over previous
#include <cuda_runtime.h>
#include <cuda_fp16.h>
#include <math.h>
#include <stdint.h>

#define N_TOK 4096
#define HDIM  1024
#define FDIM  2816
#define NEXP  8
#define NA    (N_TOK * 2)      // assignments (top-2)
#define TM    128              // m-tile rows
#define KB    64               // k halves per chunk = 128 B per smem row
#define STAGE 32768            // A tile 16KB + B tile 16KB
#define NSTG  3
#define SMEM_DYN (NSTG * STAGE)
#define MAXMT 72               // max total m-tiles: 8192/128 + 7

// ---------------- scratch (static device allocations only) ----------------
__device__ float g_scores[NA];
__device__ int   g_eids[NA];
__device__ int   g_cnt[NEXP];
__device__ int   g_fill[NEXP];
__device__ int   g_off[NEXP + 1];
__device__ int   g_tileoff[NEXP + 1];
__device__ int   g_rows[NA];     // sorted pos -> token
__device__ int   g_aid[NA];      // sorted pos -> assignment id
__device__ __align__(16) __half g_xh[(size_t)N_TOK * HDIM];
__device__ __align__(16) __half g_w1h[(size_t)NEXP * 2 * FDIM * HDIM];
__device__ __align__(16) __half g_w2h[(size_t)NEXP * HDIM * FDIM];
__device__ __align__(16) __half g_Gh[(size_t)NA * FDIM];   // GLU output fp16

// ---------------- helpers ----------------
__device__ __forceinline__ uint32_t smem_u32(const void* p) {
    uint32_t a;
    asm("{ .reg .u64 t; cvta.to.shared.u64 t, %1; cvt.u32.u64 %0, t; }" : "=r"(a) : "l"(p));
    return a;
}
__device__ __forceinline__ uint32_t sw(uint32_t off) {   // SW128 swizzle: chunk ^= row&7
    return off ^ ((off >> 3) & 0x70);
}
#define CP16(dst, src) \
    asm volatile("cp.async.cg.shared.global [%0], [%1], 16;" :: "r"(dst), "l"(src))
#define CPCOMMIT() asm volatile("cp.async.commit_group;" ::: "memory")
#define CPWAIT1()  asm volatile("cp.async.wait_group 1;" ::: "memory")
#define CPWAIT0()  asm volatile("cp.async.wait_group 0;" ::: "memory")
#define LDM4(r0, r1, r2, r3, addr) \
    asm volatile("ldmatrix.sync.aligned.m8n8.x4.shared.b16 {%0,%1,%2,%3},[%4];" \
                 : "=r"(r0), "=r"(r1), "=r"(r2), "=r"(r3) : "r"(addr))
__device__ __forceinline__ void mma16(float* d, const uint32_t* a, uint32_t b0, uint32_t b1) {
    asm volatile(
        "mma.sync.aligned.m16n8k16.row.col.f32.f16.f16.f32 "
        "{%0,%1,%2,%3},{%4,%5,%6,%7},{%8,%9},{%0,%1,%2,%3};"
        : "+f"(d[0]), "+f"(d[1]), "+f"(d[2]), "+f"(d[3])
        : "r"(a[0]), "r"(a[1]), "r"(a[2]), "r"(a[3]), "r"(b0), "r"(b1));
}
// fragment loads (A: 2 x ldmatrix.x4 by mi; B: 1 x ldmatrix.x4 per (j,p))
#define LDAF(dst, sbase, j) do { \
    LDM4((dst)[0][0], (dst)[0][1], (dst)[0][2], (dst)[0][3], (sbase) + sw(aoff[0] + (j) * 32)); \
    LDM4((dst)[1][0], (dst)[1][1], (dst)[1][2], (dst)[1][3], (sbase) + sw(aoff[1] + (j) * 32)); \
} while (0)
#define LDBF(dst, sbase, j, p) \
    LDM4((dst)[0], (dst)[1], (dst)[2], (dst)[3], (sbase) + sw(boff[p] + (j) * 32))

// ---------------- launch 0: fp32 -> fp16 weight convert (+ counter init) ------
__global__ void convert_kernel(const float* __restrict__ w1, const float* __restrict__ w2) {
    if (blockIdx.x == 0 && threadIdx.x < NEXP) {
        g_cnt[threadIdx.x] = 0; g_fill[threadIdx.x] = 0;
    }
    const size_t U1 = (size_t)NEXP * 2 * FDIM * HDIM / 8;
    const size_t U2 = (size_t)NEXP * HDIM * FDIM / 8;
    const size_t i = (size_t)blockIdx.x * blockDim.x + threadIdx.x;
    const float* src;
    __half* dst;
    if (i < U1)           { src = w1 + i * 8;        dst = g_w1h + i * 8; }
    else if (i < U1 + U2) { src = w2 + (i - U1) * 8; dst = g_w2h + (i - U1) * 8; }
    else return;
    const float4 v0 = ((const float4*)src)[0];
    const float4 v1 = ((const float4*)src)[1];
    __half2 h0 = __floats2half2_rn(v0.x, v0.y);
    __half2 h1 = __floats2half2_rn(v0.z, v0.w);
    __half2 h2 = __floats2half2_rn(v1.x, v1.y);
    __half2 h3 = __floats2half2_rn(v1.z, v1.w);
    uint4 o;
    o.x = *(uint32_t*)&h0; o.y = *(uint32_t*)&h1;
    o.z = *(uint32_t*)&h2; o.w = *(uint32_t*)&h3;
    *(uint4*)dst = o;
}

// ---------------- launch 1: router (+ x fp16 convert) ----------------
__global__ __launch_bounds__(256) void router_kernel(const float* __restrict__ x,
                                                     const float* __restrict__ wqkv) {
    __shared__ float sx[HDIM];
    __shared__ float sqkv[3 * NEXP];
    const int t = blockIdx.x;
    const float* xr = x + (size_t)t * HDIM;
    for (int i = threadIdx.x; i < HDIM; i += blockDim.x) sx[i] = xr[i];
    __syncthreads();

    for (int i = threadIdx.x; i < HDIM; i += blockDim.x)
        g_xh[(size_t)t * HDIM + i] = __float2half(sx[i]);

    const int w = threadIdx.x >> 5, lane = threadIdx.x & 31;
    #pragma unroll
    for (int r = 0; r < 3; r++) {
        const int j = w + r * NEXP;
        const float* wr = wqkv + (size_t)j * HDIM;
        float s = 0.f;
        for (int i = lane; i < HDIM; i += 32) s += sx[i] * wr[i];
        #pragma unroll
        for (int o = 16; o; o >>= 1) s += __shfl_xor_sync(0xffffffffu, s, o);
        if (lane == 0) sqkv[j] = s;
    }
    __syncthreads();

    if (w == 0) {
        float logit = -1e30f;
        if (lane < NEXP) {
            const float qe = sqkv[lane];
            float a[NEXP], m = -1e30f;
            #pragma unroll
            for (int j = 0; j < NEXP; j++) { a[j] = qe * sqkv[8 + j]; m = fmaxf(m, a[j]); }
            float den = 0.f, num = 0.f;
            #pragma unroll
            for (int j = 0; j < NEXP; j++) {
                float ee = expf(a[j] - m);
                den += ee; num += ee * sqkv[16 + j];
            }
            logit = num / den;
        }
        float lg[NEXP];
        #pragma unroll
        for (int e = 0; e < NEXP; e++) lg[e] = __shfl_sync(0xffffffffu, logit, e);
        if (lane == 0) {
            int i0 = 0;
            #pragma unroll
            for (int e = 1; e < NEXP; e++) if (lg[e] > lg[i0]) i0 = e;
            int i1 = (i0 == 0) ? 1 : 0;
            #pragma unroll
            for (int e = 0; e < NEXP; e++) if (e != i1 && e != i0 && lg[e] > lg[i1]) i1 = e;
            const float e1 = expf(lg[i1] - lg[i0]);
            const float inv = 1.f / (1.f + e1);
            g_scores[2 * t]     = inv;
            g_scores[2 * t + 1] = e1 * inv;
            g_eids[2 * t]     = i0;
            g_eids[2 * t + 1] = i1;
            atomicAdd(&g_cnt[i0], 1);
            atomicAdd(&g_cnt[i1], 1);
        }
    }
}

// ---------------- launch 2: scatter (each block re-derives the 8-expert scan) --
__global__ void scatter_kernel() {
    int off[NEXP + 1], tileoff[NEXP + 1];
    int o = 0, tt = 0;
    #pragma unroll
    for (int e = 0; e < NEXP; e++) {
        off[e] = o; tileoff[e] = tt;
        o += g_cnt[e];
        tt += (g_cnt[e] + TM - 1) / TM;
    }
    off[NEXP] = o; tileoff[NEXP] = tt;

    if (blockIdx.x == 0 && threadIdx.x == 0) {
        #pragma unroll
        for (int e = 0; e <= NEXP; e++) { g_off[e] = off[e]; g_tileoff[e] = tileoff[e]; }
    }

    const int a = blockIdx.x * blockDim.x + threadIdx.x;
    if (a < NA) {
        const int e = g_eids[a];
        const int p = off[e] + atomicAdd(&g_fill[e], 1);
        g_aid[p]  = a;
        g_rows[p] = a >> 1;
    }
}

// ---------------- launch 3: grouped GEMM1 (fp16 HMMA) + fused GLU -------------
// 256 threads, M=128 x 64 GLU cols; deep-pipelined fragments:
//   B: ring-3, prefetch distance 2;  A: ping-pong, prefetch at p==1 (distance 3)
__global__ __launch_bounds__(256, 2) void gemm1_kernel() {
    const int mt = blockIdx.x;
    if (mt >= g_tileoff[NEXP]) return;
    int e = 0;
    #pragma unroll
    for (int i = 1; i < NEXP; i++) if (g_tileoff[i] <= mt) e = i;
    const int pbase = g_off[e];
    const int cnt   = g_off[e + 1] - pbase;
    const int m0    = (mt - g_tileoff[e]) * TM;
    const int nb    = blockIdx.y * 64;            // GLU col base

    extern __shared__ __align__(1024) char smem[];
    const uint32_t sb = smem_u32(smem);
    const int tid = threadIdx.x, wid = tid >> 5, lane = tid & 31;
    const int wm = wid & 3, wn = wid >> 2;
    const int sel = lane >> 3, li = lane & 7;
    const int g = lane >> 2, tg = lane & 3;

    const int r = tid >> 1, hh = tid & 1;
    int am = m0 + r; if (am >= cnt) am = cnt - 1;
    const char* asrc = (const char*)(g_xh + (size_t)g_rows[pbase + am] * HDIM) + hh * 64;
    const int wrow = e * 2 * FDIM + ((r & 1) ? FDIM : 0) + nb + (r >> 1);  // a/g interleave
    const char* bsrc = (const char*)(g_w1h + (size_t)wrow * HDIM) + hh * 64;
    uint32_t adst[4], bdst[4];
    #pragma unroll
    for (int i = 0; i < 4; i++) {
        const uint32_t off = r * 128 + hh * 64 + i * 16;
        adst[i] = sw(off);
        bdst[i] = 16384 + sw(off);
    }

    uint32_t aoff[2], boff[4];
    #pragma unroll
    for (int mi = 0; mi < 2; mi++)
        aoff[mi] = (uint32_t)(wm * 32 + mi * 16 + (sel & 1) * 8 + li) * 128 + (sel >> 1) * 16;
    #pragma unroll
    for (int p = 0; p < 4; p++)
        boff[p] = 16384 + (uint32_t)(wn * 64 + p * 16 + (sel >> 1) * 8 + li) * 128 + (sel & 1) * 16;

    float acc[2][8][4];
    #pragma unroll
    for (int mi = 0; mi < 2; mi++)
        #pragma unroll
        for (int ni = 0; ni < 8; ni++)
            #pragma unroll
            for (int q = 0; q < 4; q++) acc[mi][ni][q] = 0.f;

    auto stage = [&](int c, int s) {
        const uint32_t base = sb + s * STAGE;
        const char* ga = asrc + (size_t)c * 128;
        const char* gb = bsrc + (size_t)c * 128;
        #pragma unroll
        for (int i = 0; i < 4; i++) CP16(base + adst[i], ga + i * 16);
        #pragma unroll
        for (int i = 0; i < 4; i++) CP16(base + bdst[i], gb + i * 16);
        CPCOMMIT();
    };

    uint32_t af[2][2][4], bf[3][4];
    const int NC = HDIM / KB;  // 16
    stage(0, 0); stage(1, 1);
    CPWAIT1();
    __syncthreads();

    for (int c = 0; c < NC; c++) {
        const uint32_t sbase = sb + (c % NSTG) * STAGE;
        // chunk-head fragment loads
        LDAF(af[0], sbase, 0);
        LDBF(bf[0], sbase, 0, 0);
        LDBF(bf[1], sbase, 0, 1);
        #pragma unroll
        for (int t = 0; t < 16; t++) {
            const int j = t >> 2, p = t & 3;
            if (t + 2 < 16) LDBF(bf[(t + 2) % 3], sbase, (t + 2) >> 2, (t + 2) & 3);
            if (p == 1 && j < 3) LDAF(af[(j + 1) & 1], sbase, j + 1);
            #pragma unroll
            for (int mi = 0; mi < 2; mi++) {
                mma16(acc[mi][2 * p],     af[j & 1][mi], bf[t % 3][0], bf[t % 3][1]);
                mma16(acc[mi][2 * p + 1], af[j & 1][mi], bf[t % 3][2], bf[t % 3][3]);
            }
        }
        if (c + 1 < NC) {
            if (c + 2 < NC) { stage(c + 2, (c + 2) % NSTG); CPWAIT1(); }
            else            { CPWAIT0(); }
            __syncthreads();
        }
    }

    // GLU epilogue: d even col = a, odd col = g of GLU col (n/2)
    #pragma unroll
    for (int mi = 0; mi < 2; mi++)
        #pragma unroll
        for (int h = 0; h < 2; h++) {
            const int m = m0 + wm * 32 + mi * 16 + g + h * 8;
            if (m < cnt) {
                __half* gp = g_Gh + (size_t)(pbase + m) * FDIM + nb + wn * 32;
                #pragma unroll
                for (int ni = 0; ni < 8; ni++) {
                    const float a  = acc[mi][ni][h * 2];
                    const float gg = acc[mi][ni][h * 2 + 1];
                    gp[ni * 4 + tg] = __float2half(a / (1.f + expf(-a)) * gg);
                }
            }
        }
}

// ---------------- launch 4: zero output ----------------
__global__ void zero_kernel(float* __restrict__ out) {
    const int i = blockIdx.x * blockDim.x + threadIdx.x;
    if (i < N_TOK * HDIM / 4) ((float4*)out)[i] = make_float4(0.f, 0.f, 0.f, 0.f);
}

// ---------------- launch 5: grouped GEMM2 (fp16 HMMA) + score + atomic combine
__global__ __launch_bounds__(256, 2) void gemm2_kernel(float* __restrict__ out) {
    const int mt = blockIdx.x;
    if (mt >= g_tileoff[NEXP]) return;
    int e = 0;
    #pragma unroll
    for (int i = 1; i < NEXP; i++) if (g_tileoff[i] <= mt) e = i;
    const int pbase = g_off[e];
    const int cnt   = g_off[e + 1] - pbase;
    const int m0    = (mt - g_tileoff[e]) * TM;
    const int nb    = blockIdx.y * 128;           // output col base

    extern __shared__ __align__(1024) char smem[];
    const uint32_t sb = smem_u32(smem);
    const int tid = threadIdx.x, wid = tid >> 5, lane = tid & 31;
    const int wm = wid & 3, wn = wid >> 2;
    const int sel = lane >> 3, li = lane & 7;
    const int g = lane >> 2, tg = lane & 3;

    const int r = tid >> 1, hh = tid & 1;
    int am = m0 + r; if (am >= cnt) am = cnt - 1;
    const char* asrc = (const char*)(g_Gh + (size_t)(pbase + am) * FDIM) + hh * 64;
    const char* bsrc = (const char*)(g_w2h + ((size_t)e * HDIM + nb + r) * FDIM) + hh * 64;
    uint32_t adst[4], bdst[4];
    #pragma unroll
    for (int i = 0; i < 4; i++) {
        const uint32_t off = r * 128 + hh * 64 + i * 16;
        adst[i] = sw(off);
        bdst[i] = 16384 + sw(off);
    }

    uint32_t aoff[2], boff[4];
    #pragma unroll
    for (int mi = 0; mi < 2; mi++)
        aoff[mi] = (uint32_t)(wm * 32 + mi * 16 + (sel & 1) * 8 + li) * 128 + (sel >> 1) * 16;
    #pragma unroll
    for (int p = 0; p < 4; p++)
        boff[p] = 16384 + (uint32_t)(wn * 64 + p * 16 + (sel >> 1) * 8 + li) * 128 + (sel & 1) * 16;

    float acc[2][8][4];
    #pragma unroll
    for (int mi = 0; mi < 2; mi++)
        #pragma unroll
        for (int ni = 0; ni < 8; ni++)
            #pragma unroll
            for (int q = 0; q < 4; q++) acc[mi][ni][q] = 0.f;

    auto stage = [&](int c, int s) {
        const uint32_t base = sb + s * STAGE;
        const char* ga = asrc + (size_t)c * 128;
        const char* gb = bsrc + (size_t)c * 128;
        #pragma unroll
        for (int i = 0; i < 4; i++) CP16(base + adst[i], ga + i * 16);
        #pragma unroll
        for (int i = 0; i < 4; i++) CP16(base + bdst[i], gb + i * 16);
        CPCOMMIT();
    };

    uint32_t af[2][2][4], bf[3][4];
    const int NC = FDIM / KB;  // 44
    stage(0, 0); stage(1, 1);
    CPWAIT1();
    __syncthreads();

    for (int c = 0; c < NC; c++) {
        const uint32_t sbase = sb + (c % NSTG) * STAGE;
        LDAF(af[0], sbase, 0);
        LDBF(bf[0], sbase, 0, 0);
        LDBF(bf[1], sbase, 0, 1);
        #pragma unroll
        for (int t = 0; t < 16; t++) {
            const int j = t >> 2, p = t & 3;
            if (t + 2 < 16) LDBF(bf[(t + 2) % 3], sbase, (t + 2) >> 2, (t + 2) & 3);
            if (p == 1 && j < 3) LDAF(af[(j + 1) & 1], sbase, j + 1);
            #pragma unroll
            for (int mi = 0; mi < 2; mi++) {
                mma16(acc[mi][2 * p],     af[j & 1][mi], bf[t % 3][0], bf[t % 3][1]);
                mma16(acc[mi][2 * p + 1], af[j & 1][mi], bf[t % 3][2], bf[t % 3][3]);
            }
        }
        if (c + 1 < NC) {
            if (c + 2 < NC) { stage(c + 2, (c + 2) % NSTG); CPWAIT1(); }
            else            { CPWAIT0(); }
            __syncthreads();
        }
    }

    // epilogue: scale by routing score, atomic top-2 combine (2 adds/cell -> deterministic)
    #pragma unroll
    for (int mi = 0; mi < 2; mi++)
        #pragma unroll
        for (int h = 0; h < 2; h++) {
            const int m = m0 + wm * 32 + mi * 16 + g + h * 8;
            if (m < cnt) {
                const int aid  = g_aid[pbase + m];
                const float sc = g_scores[aid];
                float* op = out + (size_t)(aid >> 1) * HDIM + nb + wn * 64;
                #pragma unroll
                for (int ni = 0; ni < 8; ni++) {
                    const int c0 = ni * 8 + 2 * tg;
                    atomicAdd(op + c0,     sc * acc[mi][ni][h * 2]);
                    atomicAdd(op + c0 + 1, sc * acc[mi][ni][h * 2 + 1]);
                }
            }
        }
}

// ---------------- launch ----------------
extern "C" void kernel_launch(void* const* d_in, const int* in_sizes, int n_in,
                              void* d_out, int out_size) {
    const float* x    = (const float*)d_in[0];  // (2,2048,1024)
    const float* wqkv = (const float*)d_in[1];  // (24,1024)
    const float* w1   = (const float*)d_in[2];  // (8,5632,1024)
    const float* w2   = (const float*)d_in[3];  // (8,1024,2816)
    float* out = (float*)d_out;

    cudaFuncSetAttribute(gemm1_kernel, cudaFuncAttributeMaxDynamicSharedMemorySize, SMEM_DYN);
    cudaFuncSetAttribute(gemm2_kernel, cudaFuncAttributeMaxDynamicSharedMemorySize, SMEM_DYN);

    const int conv_units = (NEXP * 2 * FDIM * HDIM + NEXP * HDIM * FDIM) / 8;
    convert_kernel<<<(conv_units + 255) / 256, 256>>>(w1, w2);            // 0
    router_kernel<<<N_TOK, 256>>>(x, wqkv);                               // 1
    scatter_kernel<<<(NA + 255) / 256, 256>>>();                          // 2
    gemm1_kernel<<<dim3(MAXMT, FDIM / 64), 256, SMEM_DYN>>>();            // 3  <- profiled
    zero_kernel<<<(N_TOK * HDIM / 4 + 255) / 256, 256>>>(out);            // 4
    gemm2_kernel<<<dim3(MAXMT, HDIM / 128), 256, SMEM_DYN>>>(out);        // 5
}